// round 1
// baseline (speedup 1.0000x reference)
#include <cuda_runtime.h>
#include <cuda_bf16.h>
#include <cstddef>

// ---------------------------------------------------------------------------
// SwinBlock_tp: H=W=64, WS=8, SHIFT=4, C=512, NH=16, DH=32, B=32
// Token rows M = 64*64*32 = 131072.
// Window layout row index r = s*2048 + n, s = hn*8+wn (64 windows),
// n = i*256 + j*32 + b  (in-window pos (i,j), batch b).
// ---------------------------------------------------------------------------

#define MROWS 131072
#define CDIM  512

// Scratch (device globals; no allocation allowed)
__device__ float g_xw    [ (size_t)MROWS * 512  ];   // LN1+shift+partition output
__device__ float g_qkv   [ (size_t)MROWS * 1536 ];   // qkv projection
__device__ float g_ctx   [ (size_t)MROWS * 512  ];   // attention context
__device__ float g_attn  [ (size_t)MROWS * 512  ];   // proj + residual
__device__ float g_hidden[ (size_t)MROWS * 512  ];   // shortcut + y
__device__ float g_zln   [ (size_t)MROWS * 512  ];   // LN2(hidden)
__device__ float g_fc1   [ (size_t)MROWS * 2048 ];   // gelu(fc1)

// ---------------------------------------------------------------------------
// block reduce for 128-thread LN kernels
// ---------------------------------------------------------------------------
__device__ __forceinline__ void block_reduce2(float& sum, float& sq, float* sbuf) {
    #pragma unroll
    for (int o = 16; o > 0; o >>= 1) {
        sum += __shfl_xor_sync(0xffffffffu, sum, o);
        sq  += __shfl_xor_sync(0xffffffffu, sq,  o);
    }
    int wid  = threadIdx.x >> 5;
    int lane = threadIdx.x & 31;
    if (lane == 0) { sbuf[wid] = sum; sbuf[4 + wid] = sq; }
    __syncthreads();
    sum = sbuf[0] + sbuf[1] + sbuf[2] + sbuf[3];
    sq  = sbuf[4] + sbuf[5] + sbuf[6] + sbuf[7];
}

// ---------------------------------------------------------------------------
// K1: LN1 + roll(-4,-4) + window partition.  out row r <- input row (h,w,b)
// grid = 131072 blocks, 128 threads
// ---------------------------------------------------------------------------
__global__ void ln_shift_kernel(const float* __restrict__ x,
                                const float* __restrict__ g,
                                const float* __restrict__ b,
                                float* __restrict__ out) {
    __shared__ float sbuf[8];
    int r = blockIdx.x;
    int t = threadIdx.x;
    int s  = r >> 11;            // window index
    int n  = r & 2047;
    int hn = s >> 3, wn = s & 7;
    int i  = n >> 8, j = (n >> 5) & 7, bb = n & 31;
    int h  = ((hn << 3) + i + 4) & 63;
    int w  = ((wn << 3) + j + 4) & 63;
    size_t src = ((size_t)((h << 6) + w) * 32 + bb) * 512;

    float4 xv = *(const float4*)(x + src + t * 4);
    float sum = xv.x + xv.y + xv.z + xv.w;
    float sq  = xv.x*xv.x + xv.y*xv.y + xv.z*xv.z + xv.w*xv.w;
    block_reduce2(sum, sq, sbuf);
    float mu   = sum * (1.0f / 512.0f);
    float var  = sq * (1.0f / 512.0f) - mu * mu;
    float rstd = rsqrtf(var + 1e-5f);

    float4 gv = *(const float4*)(g + t * 4);
    float4 bv = *(const float4*)(b + t * 4);
    float4 o;
    o.x = (xv.x - mu) * rstd * gv.x + bv.x;
    o.y = (xv.y - mu) * rstd * gv.y + bv.y;
    o.z = (xv.z - mu) * rstd * gv.z + bv.z;
    o.w = (xv.w - mu) * rstd * gv.w + bv.w;
    *(float4*)(out + (size_t)r * 512 + t * 4) = o;
}

// ---------------------------------------------------------------------------
// K5: window reverse + unshift + shortcut add, then LN2 -> zln. One pass.
// grid = 131072 (original token rows), 128 threads
// ---------------------------------------------------------------------------
__global__ void rev_add_ln2_kernel(const float* __restrict__ attn,
                                   const float* __restrict__ shortcut,
                                   const float* __restrict__ g,
                                   const float* __restrict__ b,
                                   float* __restrict__ hidden,
                                   float* __restrict__ zln) {
    __shared__ float sbuf[8];
    int m = blockIdx.x;
    int t = threadIdx.x;
    int bb  = m & 31;
    int tok = m >> 5;
    int h   = tok >> 6, w = tok & 63;
    int wh  = (h + 60) & 63;      // inverse of (+4 mod 64)
    int wwc = (w + 60) & 63;
    int r = ((((wh >> 3) << 3) + (wwc >> 3)) << 11) + ((wh & 7) << 8) + ((wwc & 7) << 5) + bb;

    float4 a  = *(const float4*)(attn + (size_t)r * 512 + t * 4);
    float4 sc = *(const float4*)(shortcut + (size_t)m * 512 + t * 4);
    float4 hv;
    hv.x = a.x + sc.x; hv.y = a.y + sc.y; hv.z = a.z + sc.z; hv.w = a.w + sc.w;
    *(float4*)(hidden + (size_t)m * 512 + t * 4) = hv;

    float sum = hv.x + hv.y + hv.z + hv.w;
    float sq  = hv.x*hv.x + hv.y*hv.y + hv.z*hv.z + hv.w*hv.w;
    block_reduce2(sum, sq, sbuf);
    float mu   = sum * (1.0f / 512.0f);
    float var  = sq * (1.0f / 512.0f) - mu * mu;
    float rstd = rsqrtf(var + 1e-5f);

    float4 gv = *(const float4*)(g + t * 4);
    float4 bv = *(const float4*)(b + t * 4);
    float4 o;
    o.x = (hv.x - mu) * rstd * gv.x + bv.x;
    o.y = (hv.y - mu) * rstd * gv.y + bv.y;
    o.z = (hv.z - mu) * rstd * gv.z + bv.z;
    o.w = (hv.w - mu) * rstd * gv.w + bv.w;
    *(float4*)(zln + (size_t)m * 512 + t * 4) = o;
}

// ---------------------------------------------------------------------------
// K3: attention per (n, h). seq = 64 (windows axis s), head dim 32.
// mask(n,s,t): region-id mismatch within mask-window mw = n % 64.
// grid = (2048, 16), 256 threads
// ---------------------------------------------------------------------------
__device__ __forceinline__ int region_id(int c) { return c < 56 ? 0 : (c < 60 ? 1 : 2); }

__global__ __launch_bounds__(256) void attn_kernel(const float* __restrict__ qkv,
                                                   float* __restrict__ ctx) {
    __shared__ float q[64][33];
    __shared__ float k[64][33];
    __shared__ float v[64][33];
    __shared__ float sc[64][65];
    __shared__ int   val[64];

    int n = blockIdx.x;
    int h = blockIdx.y;
    int t = threadIdx.x;

    // load q/k/v (each 64x32) from qkv rows r = s*2048+n, cols h*96 + {0,32,64}
    for (int f = t; f < 1536; f += 256) {
        int s  = f / 24;
        int c4 = (f % 24) * 4;
        const float4 x = *(const float4*)(qkv + (size_t)(s * 2048 + n) * 1536 + h * 96 + c4);
        float vv[4] = {x.x, x.y, x.z, x.w};
        #pragma unroll
        for (int z = 0; z < 4; z++) {
            int c = c4 + z;
            if (c < 32)       q[s][c]      = vv[z];
            else if (c < 64)  k[s][c - 32] = vv[z];
            else              v[s][c - 64] = vv[z];
        }
    }
    if (t < 64) {
        int mw = n & 63;
        int hh = ((mw >> 3) << 3) + (t >> 3);
        int ww = ((mw & 7) << 3) + (t & 7);
        val[t] = region_id(hh) * 3 + region_id(ww);
    }
    __syncthreads();

    // scores: thread (s = t>>2, tb = t&3) computes 16 t-values
    {
        int s  = t >> 2;
        int tb = t & 3;
        float acc[16];
        #pragma unroll
        for (int i = 0; i < 16; i++) acc[i] = 0.0f;
        for (int d = 0; d < 32; d++) {
            float qd = q[s][d];
            #pragma unroll
            for (int i = 0; i < 16; i++) acc[i] += qd * k[tb * 16 + i][d];
        }
        int vs = val[s];
        #pragma unroll
        for (int i = 0; i < 16; i++) {
            int tt = tb * 16 + i;
            float x = acc[i] * 0.17677669529663687f;   // 1/sqrt(32)
            if (val[tt] != vs) x = -10000.0f;
            sc[s][tt] = x;
        }
    }
    __syncthreads();

    // softmax: one thread per row
    if (t < 64) {
        float mx = -1e30f;
        #pragma unroll 8
        for (int j = 0; j < 64; j++) mx = fmaxf(mx, sc[t][j]);
        float sum = 0.0f;
        #pragma unroll 8
        for (int j = 0; j < 64; j++) { float e = __expf(sc[t][j] - mx); sc[t][j] = e; sum += e; }
        float inv = 1.0f / sum;
        #pragma unroll 8
        for (int j = 0; j < 64; j++) sc[t][j] *= inv;
    }
    __syncthreads();

    // ctx[s][d] = sum_j p[s][j] * v[j][d]
    #pragma unroll
    for (int i = 0; i < 8; i++) {
        int o  = i * 256 + t;
        int os = o >> 5;
        int d  = o & 31;
        float a = 0.0f;
        #pragma unroll 8
        for (int j = 0; j < 64; j++) a += sc[os][j] * v[j][d];
        ctx[(size_t)(os * 2048 + n) * 512 + h * 32 + d] = a;
    }
}

// ---------------------------------------------------------------------------
// Tiled GEMM: C[M,N] = A[M,K] @ B[K,N] + bias, epilogue variants.
// BM=128, BN=128, BK=16, 256 threads, 8x8 per thread.
// EPI: 0 = +bias; 1 = +bias+add1; 2 = gelu(+bias); 3 = +bias+add1+add2
// grid = (N/128, M/128)
// ---------------------------------------------------------------------------
__device__ __forceinline__ float gelu_exact(float x) {
    return 0.5f * x * (1.0f + erff(x * 0.70710678118654752f));
}

template<int EPI>
__global__ __launch_bounds__(256) void gemm_kernel(const float* __restrict__ A,
                                                   const float* __restrict__ B,
                                                   const float* __restrict__ bias,
                                                   const float* __restrict__ add1,
                                                   const float* __restrict__ add2,
                                                   float* __restrict__ Cout,
                                                   int N, int K) {
    __shared__ float As[16 * 132];   // transposed, padded stride 132
    __shared__ float Bs[16 * 128];

    const int m0 = blockIdx.y * 128;
    const int n0 = blockIdx.x * 128;
    const int t  = threadIdx.x;
    const int ty = t >> 4;           // 0..15  (row group)
    const int tx = t & 15;           // 0..15  (col group)

    float acc[8][8];
    #pragma unroll
    for (int i = 0; i < 8; i++)
        #pragma unroll
        for (int j = 0; j < 8; j++) acc[i][j] = 0.0f;

    for (int k0 = 0; k0 < K; k0 += 16) {
        #pragma unroll
        for (int l = 0; l < 2; l++) {
            int f   = t + l * 256;
            int row = f >> 2;
            int c4  = (f & 3) * 4;
            float4 av = *(const float4*)(A + (size_t)(m0 + row) * K + k0 + c4);
            As[(c4 + 0) * 132 + row] = av.x;
            As[(c4 + 1) * 132 + row] = av.y;
            As[(c4 + 2) * 132 + row] = av.z;
            As[(c4 + 3) * 132 + row] = av.w;
        }
        #pragma unroll
        for (int l = 0; l < 2; l++) {
            int f  = t + l * 256;
            int kk = f >> 5;
            int c4 = (f & 31) * 4;
            *(float4*)(Bs + kk * 128 + c4) =
                *(const float4*)(B + (size_t)(k0 + kk) * N + n0 + c4);
        }
        __syncthreads();

        #pragma unroll
        for (int kk = 0; kk < 16; kk++) {
            float4 a0 = *(const float4*)(As + kk * 132 + ty * 8);
            float4 a1 = *(const float4*)(As + kk * 132 + ty * 8 + 4);
            float4 b0 = *(const float4*)(Bs + kk * 128 + tx * 8);
            float4 b1 = *(const float4*)(Bs + kk * 128 + tx * 8 + 4);
            float ar[8] = {a0.x, a0.y, a0.z, a0.w, a1.x, a1.y, a1.z, a1.w};
            float br[8] = {b0.x, b0.y, b0.z, b0.w, b1.x, b1.y, b1.z, b1.w};
            #pragma unroll
            for (int i = 0; i < 8; i++)
                #pragma unroll
                for (int j = 0; j < 8; j++) acc[i][j] += ar[i] * br[j];
        }
        __syncthreads();
    }

    float4 bia0 = *(const float4*)(bias + n0 + tx * 8);
    float4 bia1 = *(const float4*)(bias + n0 + tx * 8 + 4);
    float bvv[8] = {bia0.x, bia0.y, bia0.z, bia0.w, bia1.x, bia1.y, bia1.z, bia1.w};

    #pragma unroll
    for (int i = 0; i < 8; i++) {
        size_t gm  = (size_t)(m0 + ty * 8 + i);
        size_t off = gm * N + n0 + tx * 8;
        float vo[8];
        #pragma unroll
        for (int j = 0; j < 8; j++) vo[j] = acc[i][j] + bvv[j];
        if (EPI == 1) {
            float4 r0 = *(const float4*)(add1 + off);
            float4 r1 = *(const float4*)(add1 + off + 4);
            vo[0] += r0.x; vo[1] += r0.y; vo[2] += r0.z; vo[3] += r0.w;
            vo[4] += r1.x; vo[5] += r1.y; vo[6] += r1.z; vo[7] += r1.w;
        }
        if (EPI == 2) {
            #pragma unroll
            for (int j = 0; j < 8; j++) vo[j] = gelu_exact(vo[j]);
        }
        if (EPI == 3) {
            float4 r0 = *(const float4*)(add1 + off);
            float4 r1 = *(const float4*)(add1 + off + 4);
            float4 s0 = *(const float4*)(add2 + off);
            float4 s1 = *(const float4*)(add2 + off + 4);
            vo[0] += r0.x + s0.x; vo[1] += r0.y + s0.y; vo[2] += r0.z + s0.z; vo[3] += r0.w + s0.w;
            vo[4] += r1.x + s1.x; vo[5] += r1.y + s1.y; vo[6] += r1.z + s1.z; vo[7] += r1.w + s1.w;
        }
        float4 o0 = {vo[0], vo[1], vo[2], vo[3]};
        float4 o1 = {vo[4], vo[5], vo[6], vo[7]};
        *(float4*)(Cout + off)     = o0;
        *(float4*)(Cout + off + 4) = o1;
    }
}

// ---------------------------------------------------------------------------
// Launch
// ---------------------------------------------------------------------------
extern "C" void kernel_launch(void* const* d_in, const int* in_sizes, int n_in,
                              void* d_out, int out_size) {
    const float* hs    = (const float*)d_in[0];
    const float* ln1g  = (const float*)d_in[1];
    const float* ln1b  = (const float*)d_in[2];
    const float* wqkv  = (const float*)d_in[3];
    const float* bqkv  = (const float*)d_in[4];
    const float* wproj = (const float*)d_in[5];
    const float* bproj = (const float*)d_in[6];
    const float* ln2g  = (const float*)d_in[7];
    const float* ln2b  = (const float*)d_in[8];
    const float* wfc1  = (const float*)d_in[9];
    const float* bfc1  = (const float*)d_in[10];
    const float* wfc2  = (const float*)d_in[11];
    const float* bfc2  = (const float*)d_in[12];
    float* out = (float*)d_out;

    float *p_xw, *p_qkv, *p_ctx, *p_attn, *p_hidden, *p_zln, *p_fc1;
    cudaGetSymbolAddress((void**)&p_xw,     g_xw);
    cudaGetSymbolAddress((void**)&p_qkv,    g_qkv);
    cudaGetSymbolAddress((void**)&p_ctx,    g_ctx);
    cudaGetSymbolAddress((void**)&p_attn,   g_attn);
    cudaGetSymbolAddress((void**)&p_hidden, g_hidden);
    cudaGetSymbolAddress((void**)&p_zln,    g_zln);
    cudaGetSymbolAddress((void**)&p_fc1,    g_fc1);

    // K1: LN1 + shift + partition
    ln_shift_kernel<<<MROWS, 128>>>(hs, ln1g, ln1b, p_xw);

    // K2: qkv = xw @ w_qkv + b_qkv      [131072, 1536]
    gemm_kernel<0><<<dim3(1536 / 128, MROWS / 128), 256>>>(
        p_xw, wqkv, bqkv, nullptr, nullptr, p_qkv, 1536, 512);

    // K3: windowed attention
    attn_kernel<<<dim3(2048, 16), 256>>>(p_qkv, p_ctx);

    // K4: attn_out = ctx @ w_proj + b_proj + xw
    gemm_kernel<1><<<dim3(512 / 128, MROWS / 128), 256>>>(
        p_ctx, wproj, bproj, p_xw, nullptr, p_attn, 512, 512);

    // K5: hidden = shortcut + reverse(attn_out); zln = LN2(hidden)
    rev_add_ln2_kernel<<<MROWS, 128>>>(p_attn, hs, ln2g, ln2b, p_hidden, p_zln);

    // K6: fc1 = gelu(zln @ w_fc1 + b_fc1)   [131072, 2048]
    gemm_kernel<2><<<dim3(2048 / 128, MROWS / 128), 256>>>(
        p_zln, wfc1, bfc1, nullptr, nullptr, p_fc1, 2048, 512);

    // K7: out = fc1 @ w_fc2 + b_fc2 + zln + hidden
    gemm_kernel<3><<<dim3(512 / 128, MROWS / 128), 256>>>(
        p_fc1, wfc2, bfc2, p_zln, p_hidden, out, 512, 2048);
}

// round 2
// speedup vs baseline: 1.0009x; 1.0009x over previous
#include <cuda_runtime.h>
#include <cuda_bf16.h>
#include <cstddef>

// ---------------------------------------------------------------------------
// SwinBlock_tp: H=W=64, WS=8, SHIFT=4, C=512, NH=16, DH=32, B=32
// Token rows M = 64*64*32 = 131072.
// Window layout row index r = s*2048 + n, s = hn*8+wn (64 windows),
// n = i*256 + j*32 + b  (in-window pos (i,j), batch b).
// ---------------------------------------------------------------------------

#define MROWS 131072
#define CDIM  512

// Scratch (device globals; no allocation allowed)
__device__ float g_xw    [ (size_t)MROWS * 512  ];   // LN1+shift+partition output
__device__ float g_qkv   [ (size_t)MROWS * 1536 ];   // qkv projection
__device__ float g_ctx   [ (size_t)MROWS * 512  ];   // attention context
__device__ float g_attn  [ (size_t)MROWS * 512  ];   // proj + residual
__device__ float g_hidden[ (size_t)MROWS * 512  ];   // shortcut + y
__device__ float g_zln   [ (size_t)MROWS * 512  ];   // LN2(hidden)
__device__ float g_fc1   [ (size_t)MROWS * 2048 ];   // gelu(fc1)

// ---------------------------------------------------------------------------
// block reduce for 128-thread LN kernels
// ---------------------------------------------------------------------------
__device__ __forceinline__ void block_reduce2(float& sum, float& sq, float* sbuf) {
    #pragma unroll
    for (int o = 16; o > 0; o >>= 1) {
        sum += __shfl_xor_sync(0xffffffffu, sum, o);
        sq  += __shfl_xor_sync(0xffffffffu, sq,  o);
    }
    int wid  = threadIdx.x >> 5;
    int lane = threadIdx.x & 31;
    if (lane == 0) { sbuf[wid] = sum; sbuf[4 + wid] = sq; }
    __syncthreads();
    sum = sbuf[0] + sbuf[1] + sbuf[2] + sbuf[3];
    sq  = sbuf[4] + sbuf[5] + sbuf[6] + sbuf[7];
}

// ---------------------------------------------------------------------------
// K1: LN1 + roll(-4,-4) + window partition.  out row r <- input row (h,w,b)
// grid = 131072 blocks, 128 threads
// ---------------------------------------------------------------------------
__global__ void ln_shift_kernel(const float* __restrict__ x,
                                const float* __restrict__ g,
                                const float* __restrict__ b,
                                float* __restrict__ out) {
    __shared__ float sbuf[8];
    int r = blockIdx.x;
    int t = threadIdx.x;
    int s  = r >> 11;            // window index
    int n  = r & 2047;
    int hn = s >> 3, wn = s & 7;
    int i  = n >> 8, j = (n >> 5) & 7, bb = n & 31;
    int h  = ((hn << 3) + i + 4) & 63;
    int w  = ((wn << 3) + j + 4) & 63;
    size_t src = ((size_t)((h << 6) + w) * 32 + bb) * 512;

    float4 xv = *(const float4*)(x + src + t * 4);
    float sum = xv.x + xv.y + xv.z + xv.w;
    float sq  = xv.x*xv.x + xv.y*xv.y + xv.z*xv.z + xv.w*xv.w;
    block_reduce2(sum, sq, sbuf);
    float mu   = sum * (1.0f / 512.0f);
    float var  = sq * (1.0f / 512.0f) - mu * mu;
    float rstd = rsqrtf(var + 1e-5f);

    float4 gv = *(const float4*)(g + t * 4);
    float4 bv = *(const float4*)(b + t * 4);
    float4 o;
    o.x = (xv.x - mu) * rstd * gv.x + bv.x;
    o.y = (xv.y - mu) * rstd * gv.y + bv.y;
    o.z = (xv.z - mu) * rstd * gv.z + bv.z;
    o.w = (xv.w - mu) * rstd * gv.w + bv.w;
    *(float4*)(out + (size_t)r * 512 + t * 4) = o;
}

// ---------------------------------------------------------------------------
// K5: window reverse + unshift + shortcut add, then LN2 -> zln. One pass.
// grid = 131072 (original token rows), 128 threads
// ---------------------------------------------------------------------------
__global__ void rev_add_ln2_kernel(const float* __restrict__ attn,
                                   const float* __restrict__ shortcut,
                                   const float* __restrict__ g,
                                   const float* __restrict__ b,
                                   float* __restrict__ hidden,
                                   float* __restrict__ zln) {
    __shared__ float sbuf[8];
    int m = blockIdx.x;
    int t = threadIdx.x;
    int bb  = m & 31;
    int tok = m >> 5;
    int h   = tok >> 6, w = tok & 63;
    int wh  = (h + 60) & 63;      // inverse of (+4 mod 64)
    int wwc = (w + 60) & 63;
    int r = ((((wh >> 3) << 3) + (wwc >> 3)) << 11) + ((wh & 7) << 8) + ((wwc & 7) << 5) + bb;

    float4 a  = *(const float4*)(attn + (size_t)r * 512 + t * 4);
    float4 sc = *(const float4*)(shortcut + (size_t)m * 512 + t * 4);
    float4 hv;
    hv.x = a.x + sc.x; hv.y = a.y + sc.y; hv.z = a.z + sc.z; hv.w = a.w + sc.w;
    *(float4*)(hidden + (size_t)m * 512 + t * 4) = hv;

    float sum = hv.x + hv.y + hv.z + hv.w;
    float sq  = hv.x*hv.x + hv.y*hv.y + hv.z*hv.z + hv.w*hv.w;
    block_reduce2(sum, sq, sbuf);
    float mu   = sum * (1.0f / 512.0f);
    float var  = sq * (1.0f / 512.0f) - mu * mu;
    float rstd = rsqrtf(var + 1e-5f);

    float4 gv = *(const float4*)(g + t * 4);
    float4 bv = *(const float4*)(b + t * 4);
    float4 o;
    o.x = (hv.x - mu) * rstd * gv.x + bv.x;
    o.y = (hv.y - mu) * rstd * gv.y + bv.y;
    o.z = (hv.z - mu) * rstd * gv.z + bv.z;
    o.w = (hv.w - mu) * rstd * gv.w + bv.w;
    *(float4*)(zln + (size_t)m * 512 + t * 4) = o;
}

// ---------------------------------------------------------------------------
// K3: attention per (n, h). seq = 64 (windows axis s), head dim 32.
// mask(n,s,t): region-id mismatch within mask-window mw = n % 64.
// grid = (2048, 16), 256 threads
// ---------------------------------------------------------------------------
__device__ __forceinline__ int region_id(int c) { return c < 56 ? 0 : (c < 60 ? 1 : 2); }

__global__ __launch_bounds__(256) void attn_kernel(const float* __restrict__ qkv,
                                                   float* __restrict__ ctx) {
    __shared__ float q[64][33];
    __shared__ float k[64][33];
    __shared__ float v[64][33];
    __shared__ float sc[64][65];
    __shared__ int   val[64];

    int n = blockIdx.x;
    int h = blockIdx.y;
    int t = threadIdx.x;

    // load q/k/v (each 64x32) from qkv rows r = s*2048+n, cols h*96 + {0,32,64}
    for (int f = t; f < 1536; f += 256) {
        int s  = f / 24;
        int c4 = (f % 24) * 4;
        const float4 x = *(const float4*)(qkv + (size_t)(s * 2048 + n) * 1536 + h * 96 + c4);
        float vv[4] = {x.x, x.y, x.z, x.w};
        #pragma unroll
        for (int z = 0; z < 4; z++) {
            int c = c4 + z;
            if (c < 32)       q[s][c]      = vv[z];
            else if (c < 64)  k[s][c - 32] = vv[z];
            else              v[s][c - 64] = vv[z];
        }
    }
    if (t < 64) {
        int mw = n & 63;
        int hh = ((mw >> 3) << 3) + (t >> 3);
        int ww = ((mw & 7) << 3) + (t & 7);
        val[t] = region_id(hh) * 3 + region_id(ww);
    }
    __syncthreads();

    // scores: thread (s = t>>2, tb = t&3) computes 16 t-values
    {
        int s  = t >> 2;
        int tb = t & 3;
        float acc[16];
        #pragma unroll
        for (int i = 0; i < 16; i++) acc[i] = 0.0f;
        for (int d = 0; d < 32; d++) {
            float qd = q[s][d];
            #pragma unroll
            for (int i = 0; i < 16; i++) acc[i] += qd * k[tb * 16 + i][d];
        }
        int vs = val[s];
        #pragma unroll
        for (int i = 0; i < 16; i++) {
            int tt = tb * 16 + i;
            float x = acc[i] * 0.17677669529663687f;   // 1/sqrt(32)
            if (val[tt] != vs) x = -10000.0f;
            sc[s][tt] = x;
        }
    }
    __syncthreads();

    // softmax: one thread per row
    if (t < 64) {
        float mx = -1e30f;
        #pragma unroll 8
        for (int j = 0; j < 64; j++) mx = fmaxf(mx, sc[t][j]);
        float sum = 0.0f;
        #pragma unroll 8
        for (int j = 0; j < 64; j++) { float e = __expf(sc[t][j] - mx); sc[t][j] = e; sum += e; }
        float inv = 1.0f / sum;
        #pragma unroll 8
        for (int j = 0; j < 64; j++) sc[t][j] *= inv;
    }
    __syncthreads();

    // ctx[s][d] = sum_j p[s][j] * v[j][d]
    #pragma unroll
    for (int i = 0; i < 8; i++) {
        int o  = i * 256 + t;
        int os = o >> 5;
        int d  = o & 31;
        float a = 0.0f;
        #pragma unroll 8
        for (int j = 0; j < 64; j++) a += sc[os][j] * v[j][d];
        ctx[(size_t)(os * 2048 + n) * 512 + h * 32 + d] = a;
    }
}

// ---------------------------------------------------------------------------
// Tiled GEMM: C[M,N] = A[M,K] @ B[K,N] + bias, epilogue variants.
// BM=128, BN=128, BK=16, 256 threads, 8x8 per thread.
// EPI: 0 = +bias; 1 = +bias+add1; 2 = gelu(+bias); 3 = +bias+add1+add2
// grid = (N/128, M/128)
// ---------------------------------------------------------------------------
__device__ __forceinline__ float gelu_exact(float x) {
    return 0.5f * x * (1.0f + erff(x * 0.70710678118654752f));
}

template<int EPI>
__global__ __launch_bounds__(256) void gemm_kernel(const float* __restrict__ A,
                                                   const float* __restrict__ B,
                                                   const float* __restrict__ bias,
                                                   const float* __restrict__ add1,
                                                   const float* __restrict__ add2,
                                                   float* __restrict__ Cout,
                                                   int N, int K) {
    __shared__ float As[16 * 132];   // transposed, padded stride 132
    __shared__ float Bs[16 * 128];

    const int m0 = blockIdx.y * 128;
    const int n0 = blockIdx.x * 128;
    const int t  = threadIdx.x;
    const int ty = t >> 4;           // 0..15  (row group)
    const int tx = t & 15;           // 0..15  (col group)

    float acc[8][8];
    #pragma unroll
    for (int i = 0; i < 8; i++)
        #pragma unroll
        for (int j = 0; j < 8; j++) acc[i][j] = 0.0f;

    for (int k0 = 0; k0 < K; k0 += 16) {
        #pragma unroll
        for (int l = 0; l < 2; l++) {
            int f   = t + l * 256;
            int row = f >> 2;
            int c4  = (f & 3) * 4;
            float4 av = *(const float4*)(A + (size_t)(m0 + row) * K + k0 + c4);
            As[(c4 + 0) * 132 + row] = av.x;
            As[(c4 + 1) * 132 + row] = av.y;
            As[(c4 + 2) * 132 + row] = av.z;
            As[(c4 + 3) * 132 + row] = av.w;
        }
        #pragma unroll
        for (int l = 0; l < 2; l++) {
            int f  = t + l * 256;
            int kk = f >> 5;
            int c4 = (f & 31) * 4;
            *(float4*)(Bs + kk * 128 + c4) =
                *(const float4*)(B + (size_t)(k0 + kk) * N + n0 + c4);
        }
        __syncthreads();

        #pragma unroll
        for (int kk = 0; kk < 16; kk++) {
            float4 a0 = *(const float4*)(As + kk * 132 + ty * 8);
            float4 a1 = *(const float4*)(As + kk * 132 + ty * 8 + 4);
            float4 b0 = *(const float4*)(Bs + kk * 128 + tx * 8);
            float4 b1 = *(const float4*)(Bs + kk * 128 + tx * 8 + 4);
            float ar[8] = {a0.x, a0.y, a0.z, a0.w, a1.x, a1.y, a1.z, a1.w};
            float br[8] = {b0.x, b0.y, b0.z, b0.w, b1.x, b1.y, b1.z, b1.w};
            #pragma unroll
            for (int i = 0; i < 8; i++)
                #pragma unroll
                for (int j = 0; j < 8; j++) acc[i][j] += ar[i] * br[j];
        }
        __syncthreads();
    }

    float4 bia0 = *(const float4*)(bias + n0 + tx * 8);
    float4 bia1 = *(const float4*)(bias + n0 + tx * 8 + 4);
    float bvv[8] = {bia0.x, bia0.y, bia0.z, bia0.w, bia1.x, bia1.y, bia1.z, bia1.w};

    #pragma unroll
    for (int i = 0; i < 8; i++) {
        size_t gm  = (size_t)(m0 + ty * 8 + i);
        size_t off = gm * N + n0 + tx * 8;
        float vo[8];
        #pragma unroll
        for (int j = 0; j < 8; j++) vo[j] = acc[i][j] + bvv[j];
        if (EPI == 1) {
            float4 r0 = *(const float4*)(add1 + off);
            float4 r1 = *(const float4*)(add1 + off + 4);
            vo[0] += r0.x; vo[1] += r0.y; vo[2] += r0.z; vo[3] += r0.w;
            vo[4] += r1.x; vo[5] += r1.y; vo[6] += r1.z; vo[7] += r1.w;
        }
        if (EPI == 2) {
            #pragma unroll
            for (int j = 0; j < 8; j++) vo[j] = gelu_exact(vo[j]);
        }
        if (EPI == 3) {
            float4 r0 = *(const float4*)(add1 + off);
            float4 r1 = *(const float4*)(add1 + off + 4);
            float4 s0 = *(const float4*)(add2 + off);
            float4 s1 = *(const float4*)(add2 + off + 4);
            vo[0] += r0.x + s0.x; vo[1] += r0.y + s0.y; vo[2] += r0.z + s0.z; vo[3] += r0.w + s0.w;
            vo[4] += r1.x + s1.x; vo[5] += r1.y + s1.y; vo[6] += r1.z + s1.z; vo[7] += r1.w + s1.w;
        }
        float4 o0 = {vo[0], vo[1], vo[2], vo[3]};
        float4 o1 = {vo[4], vo[5], vo[6], vo[7]};
        *(float4*)(Cout + off)     = o0;
        *(float4*)(Cout + off + 4) = o1;
    }
}

// ---------------------------------------------------------------------------
// Launch
// ---------------------------------------------------------------------------
extern "C" void kernel_launch(void* const* d_in, const int* in_sizes, int n_in,
                              void* d_out, int out_size) {
    const float* hs    = (const float*)d_in[0];
    const float* ln1g  = (const float*)d_in[1];
    const float* ln1b  = (const float*)d_in[2];
    const float* wqkv  = (const float*)d_in[3];
    const float* bqkv  = (const float*)d_in[4];
    const float* wproj = (const float*)d_in[5];
    const float* bproj = (const float*)d_in[6];
    const float* ln2g  = (const float*)d_in[7];
    const float* ln2b  = (const float*)d_in[8];
    const float* wfc1  = (const float*)d_in[9];
    const float* bfc1  = (const float*)d_in[10];
    const float* wfc2  = (const float*)d_in[11];
    const float* bfc2  = (const float*)d_in[12];
    float* out = (float*)d_out;

    float *p_xw, *p_qkv, *p_ctx, *p_attn, *p_hidden, *p_zln, *p_fc1;
    cudaGetSymbolAddress((void**)&p_xw,     g_xw);
    cudaGetSymbolAddress((void**)&p_qkv,    g_qkv);
    cudaGetSymbolAddress((void**)&p_ctx,    g_ctx);
    cudaGetSymbolAddress((void**)&p_attn,   g_attn);
    cudaGetSymbolAddress((void**)&p_hidden, g_hidden);
    cudaGetSymbolAddress((void**)&p_zln,    g_zln);
    cudaGetSymbolAddress((void**)&p_fc1,    g_fc1);

    // K1: LN1 + shift + partition
    ln_shift_kernel<<<MROWS, 128>>>(hs, ln1g, ln1b, p_xw);

    // K2: qkv = xw @ w_qkv + b_qkv      [131072, 1536]
    gemm_kernel<0><<<dim3(1536 / 128, MROWS / 128), 256>>>(
        p_xw, wqkv, bqkv, nullptr, nullptr, p_qkv, 1536, 512);

    // K3: windowed attention
    attn_kernel<<<dim3(2048, 16), 256>>>(p_qkv, p_ctx);

    // K4: attn_out = ctx @ w_proj + b_proj + xw
    gemm_kernel<1><<<dim3(512 / 128, MROWS / 128), 256>>>(
        p_ctx, wproj, bproj, p_xw, nullptr, p_attn, 512, 512);

    // K5: hidden = shortcut + reverse(attn_out); zln = LN2(hidden)
    rev_add_ln2_kernel<<<MROWS, 128>>>(p_attn, hs, ln2g, ln2b, p_hidden, p_zln);

    // K6: fc1 = gelu(zln @ w_fc1 + b_fc1)   [131072, 2048]
    gemm_kernel<2><<<dim3(2048 / 128, MROWS / 128), 256>>>(
        p_zln, wfc1, bfc1, nullptr, nullptr, p_fc1, 2048, 512);

    // K7: out = fc1 @ w_fc2 + b_fc2 + zln + hidden
    gemm_kernel<3><<<dim3(512 / 128, MROWS / 128), 256>>>(
        p_fc1, wfc2, bfc2, p_zln, p_hidden, out, 512, 2048);
}

// round 5
// speedup vs baseline: 5.1108x; 5.1064x over previous
#include <cuda_runtime.h>
#include <cuda_fp16.h>
#include <cstdint>
#include <cstddef>

// ===========================================================================
// SwinBlock_tp on GB300 — fp16 mma.sync GEMMs (tcgen05 unavailable: harness
// compiles PTX for compute_103 without the 'a' feature set).
// M = 131072 rows, C = 512.
// ===========================================================================

#define MROWS 131072

// ------------------------- scratch (device globals) ------------------------
__device__ __half g_xw [(size_t)MROWS * 512];
__device__ __half g_qkv[(size_t)MROWS * 1536];
__device__ __half g_ctx[(size_t)MROWS * 512];
__device__ float  g_attn[(size_t)MROWS * 512];
__device__ float  g_hid [(size_t)MROWS * 512];
__device__ __half g_zln[(size_t)MROWS * 512];
__device__ __half g_fc1[(size_t)MROWS * 2048];
// transposed weights [N][K] fp16
__device__ __half g_wq[1536 * 512];
__device__ __half g_wp[512 * 512];
__device__ __half g_w1[2048 * 512];
__device__ __half g_w2[512 * 2048];

// ------------------------------ PTX helpers --------------------------------
__device__ __forceinline__ uint32_t smem_u32(const void* p) {
    uint32_t a;
    asm("{ .reg .u64 t; cvta.to.shared.u64 t, %1; cvt.u32.u64 %0, t; }" : "=r"(a) : "l"(p));
    return a;
}
__device__ __forceinline__ void cp16(uint32_t dst, const void* src) {
    asm volatile("cp.async.cg.shared.global [%0], [%1], 16;\n" :: "r"(dst), "l"(src) : "memory");
}
#define CP_COMMIT() asm volatile("cp.async.commit_group;\n" ::: "memory")
template<int N> __device__ __forceinline__ void cp_wait() {
    asm volatile("cp.async.wait_group %0;\n" :: "n"(N) : "memory");
}
__device__ __forceinline__ void ldsm4(uint32_t* r, uint32_t addr) {
    asm volatile("ldmatrix.sync.aligned.m8n8.x4.shared.b16 {%0,%1,%2,%3}, [%4];"
        : "=r"(r[0]), "=r"(r[1]), "=r"(r[2]), "=r"(r[3]) : "r"(addr));
}
__device__ __forceinline__ void ldsm2(uint32_t* r, uint32_t addr) {
    asm volatile("ldmatrix.sync.aligned.m8n8.x2.shared.b16 {%0,%1}, [%2];"
        : "=r"(r[0]), "=r"(r[1]) : "r"(addr));
}
__device__ __forceinline__ void mma16816(float* d, const uint32_t* a, const uint32_t* b) {
    asm volatile("mma.sync.aligned.m16n8k16.row.col.f32.f16.f16.f32 "
        "{%0,%1,%2,%3}, {%4,%5,%6,%7}, {%8,%9}, {%0,%1,%2,%3};"
        : "+f"(d[0]), "+f"(d[1]), "+f"(d[2]), "+f"(d[3])
        : "r"(a[0]), "r"(a[1]), "r"(a[2]), "r"(a[3]), "r"(b[0]), "r"(b[1]));
}

// ------------------------------ small helpers ------------------------------
__device__ __forceinline__ void block_reduce2(float& sum, float& sq, float* sbuf) {
    #pragma unroll
    for (int o = 16; o > 0; o >>= 1) {
        sum += __shfl_xor_sync(0xffffffffu, sum, o);
        sq  += __shfl_xor_sync(0xffffffffu, sq,  o);
    }
    int wid = threadIdx.x >> 5, lane = threadIdx.x & 31;
    if (lane == 0) { sbuf[wid] = sum; sbuf[4 + wid] = sq; }
    __syncthreads();
    sum = sbuf[0] + sbuf[1] + sbuf[2] + sbuf[3];
    sq  = sbuf[4] + sbuf[5] + sbuf[6] + sbuf[7];
}
__device__ __forceinline__ void store_h4(__half* p, size_t off,
                                         float a, float b, float c, float d) {
    __half2 h0 = __floats2half2_rn(a, b);
    __half2 h1 = __floats2half2_rn(c, d);
    uint2 u;
    u.x = *(uint32_t*)&h0; u.y = *(uint32_t*)&h1;
    *(uint2*)(p + off) = u;
}
__device__ __forceinline__ float gelu_exact(float x) {
    return 0.5f * x * (1.0f + erff(x * 0.70710678118654752f));
}

// ---------------------------------------------------------------------------
// K0: weight transpose  W[K,N] -> Wt[N,K] fp16
// ---------------------------------------------------------------------------
__global__ void wprep_kernel(const float* __restrict__ W,
                             __half* __restrict__ Wt, int K, int N) {
    __shared__ float tile[32][33];
    int kb = blockIdx.y * 32, nb = blockIdx.x * 32;
    int tx = threadIdx.x & 31, ty = threadIdx.x >> 5;
    #pragma unroll
    for (int i = ty; i < 32; i += 8)
        tile[i][tx] = W[(size_t)(kb + i) * N + nb + tx];
    __syncthreads();
    #pragma unroll
    for (int i = ty; i < 32; i += 8)
        Wt[(size_t)(nb + i) * K + kb + tx] = __float2half(tile[tx][i]);
}

// ---------------------------------------------------------------------------
// K1: LN1 + roll(-4,-4) + window partition -> fp16
// ---------------------------------------------------------------------------
__global__ void ln_shift_kernel(const float* __restrict__ x,
                                const float* __restrict__ g,
                                const float* __restrict__ b,
                                __half* __restrict__ out) {
    __shared__ float sbuf[8];
    int r = blockIdx.x, t = threadIdx.x;
    int s = r >> 11, n = r & 2047;
    int hn = s >> 3, wn = s & 7;
    int i = n >> 8, j = (n >> 5) & 7, bb = n & 31;
    int h = ((hn << 3) + i + 4) & 63;
    int w = ((wn << 3) + j + 4) & 63;
    size_t src = ((size_t)((h << 6) + w) * 32 + bb) * 512;

    float4 xv = *(const float4*)(x + src + t * 4);
    float sum = xv.x + xv.y + xv.z + xv.w;
    float sq  = xv.x*xv.x + xv.y*xv.y + xv.z*xv.z + xv.w*xv.w;
    block_reduce2(sum, sq, sbuf);
    float mu = sum * (1.0f/512.0f);
    float rstd = rsqrtf(sq * (1.0f/512.0f) - mu*mu + 1e-5f);
    float4 gv = *(const float4*)(g + t * 4);
    float4 bv = *(const float4*)(b + t * 4);
    store_h4(out, (size_t)r * 512 + t * 4,
             (xv.x - mu) * rstd * gv.x + bv.x,
             (xv.y - mu) * rstd * gv.y + bv.y,
             (xv.z - mu) * rstd * gv.z + bv.z,
             (xv.w - mu) * rstd * gv.w + bv.w);
}

// ---------------------------------------------------------------------------
// K5: window reverse + unshift + shortcut add; hidden fp32; LN2 -> fp16
// ---------------------------------------------------------------------------
__global__ void rev_add_ln2_kernel(const float* __restrict__ attn,
                                   const float* __restrict__ shortcut,
                                   const float* __restrict__ g,
                                   const float* __restrict__ b,
                                   float* __restrict__ hidden,
                                   __half* __restrict__ zln) {
    __shared__ float sbuf[8];
    int m = blockIdx.x, t = threadIdx.x;
    int bb = m & 31, tok = m >> 5;
    int h = tok >> 6, w = tok & 63;
    int wh = (h + 60) & 63, ww = (w + 60) & 63;
    int r = ((((wh >> 3) << 3) + (ww >> 3)) << 11) + ((wh & 7) << 8) + ((ww & 7) << 5) + bb;

    float4 a  = *(const float4*)(attn + (size_t)r * 512 + t * 4);
    float4 sc = *(const float4*)(shortcut + (size_t)m * 512 + t * 4);
    float4 hv = {a.x + sc.x, a.y + sc.y, a.z + sc.z, a.w + sc.w};
    *(float4*)(hidden + (size_t)m * 512 + t * 4) = hv;

    float sum = hv.x + hv.y + hv.z + hv.w;
    float sq  = hv.x*hv.x + hv.y*hv.y + hv.z*hv.z + hv.w*hv.w;
    block_reduce2(sum, sq, sbuf);
    float mu = sum * (1.0f/512.0f);
    float rstd = rsqrtf(sq * (1.0f/512.0f) - mu*mu + 1e-5f);
    float4 gv = *(const float4*)(g + t * 4);
    float4 bv = *(const float4*)(b + t * 4);
    store_h4(zln, (size_t)m * 512 + t * 4,
             (hv.x - mu) * rstd * gv.x + bv.x,
             (hv.y - mu) * rstd * gv.y + bv.y,
             (hv.z - mu) * rstd * gv.z + bv.z,
             (hv.w - mu) * rstd * gv.w + bv.w);
}

// ---------------------------------------------------------------------------
// K3: attention per (n, h). seq=64 (window axis), head dim 32, fp16 I/O.
// ---------------------------------------------------------------------------
__device__ __forceinline__ int region_id(int c) { return c < 56 ? 0 : (c < 60 ? 1 : 2); }

__global__ __launch_bounds__(256) void attn_kernel(const __half* __restrict__ qkv,
                                                   __half* __restrict__ ctx) {
    __shared__ float q[64][33];
    __shared__ float k[64][33];
    __shared__ float v[64][33];
    __shared__ float sc[64][65];
    __shared__ int   val[64];

    int n = blockIdx.x, h = blockIdx.y, t = threadIdx.x;

    for (int f = t; f < 768; f += 256) {
        int s  = f / 12;
        int c8 = (f % 12) * 8;
        uint4 raw = *(const uint4*)(qkv + (size_t)(s * 2048 + n) * 1536 + h * 96 + c8);
        const __half2* hp = (const __half2*)&raw;
        float vv[8];
        #pragma unroll
        for (int z = 0; z < 4; z++) {
            float2 f2 = __half22float2(hp[z]);
            vv[2*z] = f2.x; vv[2*z+1] = f2.y;
        }
        float (*dst)[33] = q;
        int col = c8;
        if (c8 >= 64)      { dst = v; col = c8 - 64; }
        else if (c8 >= 32) { dst = k; col = c8 - 32; }
        #pragma unroll
        for (int z = 0; z < 8; z++) dst[s][col + z] = vv[z];
    }
    if (t < 64) {
        int mw = n & 63;
        int hh = ((mw >> 3) << 3) + (t >> 3);
        int ww = ((mw & 7) << 3) + (t & 7);
        val[t] = region_id(hh) * 3 + region_id(ww);
    }
    __syncthreads();

    // scores: 4x4 register block
    {
        int s0 = (t >> 4) * 4;
        int t0 = (t & 15) * 4;
        float acc[4][4];
        #pragma unroll
        for (int i = 0; i < 4; i++)
            #pragma unroll
            for (int j = 0; j < 4; j++) acc[i][j] = 0.0f;
        for (int d = 0; d < 32; d++) {
            float qv[4], kv[4];
            #pragma unroll
            for (int i = 0; i < 4; i++) { qv[i] = q[s0 + i][d]; kv[i] = k[t0 + i][d]; }
            #pragma unroll
            for (int i = 0; i < 4; i++)
                #pragma unroll
                for (int j = 0; j < 4; j++) acc[i][j] += qv[i] * kv[j];
        }
        #pragma unroll
        for (int i = 0; i < 4; i++) {
            int vs = val[s0 + i];
            #pragma unroll
            for (int j = 0; j < 4; j++) {
                float x = acc[i][j] * 0.17677669529663687f;
                if (val[t0 + j] != vs) x = -10000.0f;
                sc[s0 + i][t0 + j] = x;
            }
        }
    }
    __syncthreads();

    // softmax: 4 threads per row
    {
        int tr = t >> 2, tq = (t & 3) * 16;
        float mx = -1e30f;
        #pragma unroll
        for (int j = 0; j < 16; j++) mx = fmaxf(mx, sc[tr][tq + j]);
        mx = fmaxf(mx, __shfl_xor_sync(0xffffffffu, mx, 1));
        mx = fmaxf(mx, __shfl_xor_sync(0xffffffffu, mx, 2));
        float sum = 0.0f;
        float e[16];
        #pragma unroll
        for (int j = 0; j < 16; j++) { e[j] = __expf(sc[tr][tq + j] - mx); sum += e[j]; }
        sum += __shfl_xor_sync(0xffffffffu, sum, 1);
        sum += __shfl_xor_sync(0xffffffffu, sum, 2);
        float inv = 1.0f / sum;
        #pragma unroll
        for (int j = 0; j < 16; j++) sc[tr][tq + j] = e[j] * inv;
    }
    __syncthreads();

    // ctx: 2 rows x 4 cols per thread
    {
        int s0 = (t >> 3) * 2;
        int d0 = (t & 7) * 4;
        float acc[2][4];
        #pragma unroll
        for (int i = 0; i < 2; i++)
            #pragma unroll
            for (int j = 0; j < 4; j++) acc[i][j] = 0.0f;
        for (int jj = 0; jj < 64; jj++) {
            float p0 = sc[s0][jj], p1 = sc[s0 + 1][jj];
            float vv[4];
            #pragma unroll
            for (int j = 0; j < 4; j++) vv[j] = v[jj][d0 + j];
            #pragma unroll
            for (int j = 0; j < 4; j++) { acc[0][j] += p0 * vv[j]; acc[1][j] += p1 * vv[j]; }
        }
        #pragma unroll
        for (int i = 0; i < 2; i++) {
            size_t off = ((size_t)((s0 + i) * 2048 + n)) * 512 + h * 32 + d0;
            store_h4(ctx, off, acc[i][0], acc[i][1], acc[i][2], acc[i][3]);
        }
    }
}

// ---------------------------------------------------------------------------
// hgemm: out[M,Ntot] = A[M,K](fp16) @ Wt[Ntot,K](fp16)^T + bias (+epilogue)
// BM=BN=128, BK=32, 8 warps (2m x 4n), warp tile 64x32, mma.m16n8k16.
// smem rows: 64B data + 16B pad (pitch 80B) -> conflict-free LDSM.
// EPI: 0 fp16 out; 1 fp32 out + rh; 2 gelu -> fp16; 3 fp32 out + rh + r32
// ---------------------------------------------------------------------------
#define APITCH   80
#define TILE_B   (128 * APITCH)     // 10240
#define STAGE_B  (2 * TILE_B)       // 20480
#define NSTAGE   4
#define SMEM_T   (NSTAGE * STAGE_B) // 81920

__device__ __forceinline__ void load_stage(uint32_t sm, int stage,
                                           const __half* A, const __half* Bt,
                                           int K, int m0, int n0, int kk, int t) {
    uint32_t ab = sm + stage * STAGE_B;
    uint32_t bb = ab + TILE_B;
    #pragma unroll
    for (int i = 0; i < 2; i++) {
        int f = t + i * 256;
        int row = f >> 2, seg = f & 3;
        cp16(ab + row * APITCH + seg * 16, A + (size_t)(m0 + row) * K + kk + seg * 8);
    }
    #pragma unroll
    for (int i = 0; i < 2; i++) {
        int f = t + i * 256;
        int row = f >> 2, seg = f & 3;
        cp16(bb + row * APITCH + seg * 16, Bt + (size_t)(n0 + row) * K + kk + seg * 8);
    }
    CP_COMMIT();
}

template<int EPI>
__global__ void __launch_bounds__(256) hgemm(
    const __half* __restrict__ A, const __half* __restrict__ Bt,
    const float* __restrict__ bias,
    const float* __restrict__ r32, const __half* __restrict__ rh,
    float* __restrict__ out32, __half* __restrict__ outh,
    int Ntot, int K)
{
    extern __shared__ char smem[];
    uint32_t sm = smem_u32(smem);
    int t = threadIdx.x;
    int lane = t & 31, wid = t >> 5;
    int wm = wid & 1, wn = wid >> 1;
    int m0 = blockIdx.y * 128;
    int n0 = blockIdx.x * 128;
    int NI = K / 32;

    float d[4][4][4];
    #pragma unroll
    for (int a = 0; a < 4; a++)
        #pragma unroll
        for (int b = 0; b < 4; b++)
            #pragma unroll
            for (int c = 0; c < 4; c++) d[a][b][c] = 0.0f;

    load_stage(sm, 0, A, Bt, K, m0, n0, 0, t);
    load_stage(sm, 1, A, Bt, K, m0, n0, 32, t);
    load_stage(sm, 2, A, Bt, K, m0, n0, 64, t);

    for (int it = 0; it < NI; it++) {
        cp_wait<2>();
        __syncthreads();
        if (it + 3 < NI) load_stage(sm, (it + 3) & 3, A, Bt, K, m0, n0, (it + 3) * 32, t);
        else CP_COMMIT();

        uint32_t ab = sm + (it & 3) * STAGE_B;
        uint32_t bb = ab + TILE_B;
        #pragma unroll
        for (int ks = 0; ks < 2; ks++) {
            uint32_t af[4][4], bf[4][2];
            #pragma unroll
            for (int mt = 0; mt < 4; mt++) {
                int row = wm * 64 + mt * 16 + (lane & 15);
                int seg = ks * 2 + (lane >> 4);
                ldsm4(af[mt], ab + row * APITCH + seg * 16);
            }
            #pragma unroll
            for (int nt = 0; nt < 4; nt++) {
                int l = lane & 15;
                int row = wn * 32 + nt * 8 + (l & 7);
                int seg = ks * 2 + (l >> 3);
                ldsm2(bf[nt], bb + row * APITCH + seg * 16);
            }
            #pragma unroll
            for (int mt = 0; mt < 4; mt++)
                #pragma unroll
                for (int nt = 0; nt < 4; nt++)
                    mma16816(d[mt][nt], af[mt], bf[nt]);
        }
        __syncthreads();
    }

    // ---------------- epilogue ----------------
    #pragma unroll
    for (int mt = 0; mt < 4; mt++) {
        int r0 = m0 + wm * 64 + mt * 16 + (lane >> 2);
        #pragma unroll
        for (int hf = 0; hf < 2; hf++) {
            size_t gr = (size_t)(r0 + hf * 8) * Ntot;
            #pragma unroll
            for (int nt = 0; nt < 4; nt++) {
                int c = n0 + wn * 32 + nt * 8 + (lane & 3) * 2;
                float2 bv = *(const float2*)(bias + c);
                float x = d[mt][nt][hf * 2 + 0] + bv.x;
                float y = d[mt][nt][hf * 2 + 1] + bv.y;
                size_t off = gr + c;
                if (EPI == 0) {
                    *(__half2*)(outh + off) = __floats2half2_rn(x, y);
                } else if (EPI == 1) {
                    float2 rv = __half22float2(*(const __half2*)(rh + off));
                    float2 o = {x + rv.x, y + rv.y};
                    *(float2*)(out32 + off) = o;
                } else if (EPI == 2) {
                    *(__half2*)(outh + off) = __floats2half2_rn(gelu_exact(x), gelu_exact(y));
                } else {
                    float2 rv = __half22float2(*(const __half2*)(rh + off));
                    float2 hv = *(const float2*)(r32 + off);
                    float2 o = {x + rv.x + hv.x, y + rv.y + hv.y};
                    *(float2*)(out32 + off) = o;
                }
            }
        }
    }
}

// ---------------------------------------------------------------------------
// Launch
// ---------------------------------------------------------------------------
extern "C" void kernel_launch(void* const* d_in, const int* in_sizes, int n_in,
                              void* d_out, int out_size) {
    const float* hs    = (const float*)d_in[0];
    const float* ln1g  = (const float*)d_in[1];
    const float* ln1b  = (const float*)d_in[2];
    const float* wqkv  = (const float*)d_in[3];
    const float* bqkv  = (const float*)d_in[4];
    const float* wproj = (const float*)d_in[5];
    const float* bproj = (const float*)d_in[6];
    const float* ln2g  = (const float*)d_in[7];
    const float* ln2b  = (const float*)d_in[8];
    const float* wfc1  = (const float*)d_in[9];
    const float* bfc1  = (const float*)d_in[10];
    const float* wfc2  = (const float*)d_in[11];
    const float* bfc2  = (const float*)d_in[12];
    float* out = (float*)d_out;

    __half *p_xw, *p_qkv, *p_ctx, *p_zln, *p_fc1, *p_wq, *p_wp, *p_w1, *p_w2;
    float *p_attn, *p_hid;
    cudaGetSymbolAddress((void**)&p_xw,  g_xw);
    cudaGetSymbolAddress((void**)&p_qkv, g_qkv);
    cudaGetSymbolAddress((void**)&p_ctx, g_ctx);
    cudaGetSymbolAddress((void**)&p_attn, g_attn);
    cudaGetSymbolAddress((void**)&p_hid, g_hid);
    cudaGetSymbolAddress((void**)&p_zln, g_zln);
    cudaGetSymbolAddress((void**)&p_fc1, g_fc1);
    cudaGetSymbolAddress((void**)&p_wq,  g_wq);
    cudaGetSymbolAddress((void**)&p_wp,  g_wp);
    cudaGetSymbolAddress((void**)&p_w1,  g_w1);
    cudaGetSymbolAddress((void**)&p_w2,  g_w2);

    cudaFuncSetAttribute(hgemm<0>, cudaFuncAttributeMaxDynamicSharedMemorySize, SMEM_T);
    cudaFuncSetAttribute(hgemm<1>, cudaFuncAttributeMaxDynamicSharedMemorySize, SMEM_T);
    cudaFuncSetAttribute(hgemm<2>, cudaFuncAttributeMaxDynamicSharedMemorySize, SMEM_T);
    cudaFuncSetAttribute(hgemm<3>, cudaFuncAttributeMaxDynamicSharedMemorySize, SMEM_T);

    // weight transpose -> fp16 [N][K]
    wprep_kernel<<<dim3(1536/32, 512/32), 256>>>(wqkv, p_wq, 512, 1536);
    wprep_kernel<<<dim3(512/32, 512/32),  256>>>(wproj, p_wp, 512, 512);
    wprep_kernel<<<dim3(2048/32, 512/32), 256>>>(wfc1, p_w1, 512, 2048);
    wprep_kernel<<<dim3(512/32, 2048/32), 256>>>(wfc2, p_w2, 2048, 512);

    // LN1 + shift + partition
    ln_shift_kernel<<<MROWS, 128>>>(hs, ln1g, ln1b, p_xw);

    // qkv = xw @ Wqkv + b           -> fp16
    hgemm<0><<<dim3(12, 1024), 256, SMEM_T>>>(p_xw, p_wq, bqkv,
        nullptr, nullptr, nullptr, p_qkv, 1536, 512);

    // attention
    attn_kernel<<<dim3(2048, 16), 256>>>(p_qkv, p_ctx);

    // attn_out = ctx @ Wproj + b + xw   -> fp32
    hgemm<1><<<dim3(4, 1024), 256, SMEM_T>>>(p_ctx, p_wp, bproj,
        nullptr, p_xw, p_attn, nullptr, 512, 512);

    // hidden = shortcut + reverse(attn_out); zln = LN2(hidden)
    rev_add_ln2_kernel<<<MROWS, 128>>>(p_attn, hs, ln2g, ln2b, p_hid, p_zln);

    // fc1 = gelu(zln @ Wfc1 + b)    -> fp16
    hgemm<2><<<dim3(16, 1024), 256, SMEM_T>>>(p_zln, p_w1, bfc1,
        nullptr, nullptr, nullptr, p_fc1, 2048, 512);

    // out = fc1 @ Wfc2 + b + zln + hidden
    hgemm<3><<<dim3(4, 1024), 256, SMEM_T>>>(p_fc1, p_w2, bfc2,
        p_hid, p_zln, out, nullptr, 512, 2048);
}